// round 8
// baseline (speedup 1.0000x reference)
#include <cuda_runtime.h>
#include <cstdint>
#include <math.h>

#define BB   16
#define CIN  64
#define HH   64
#define WW   64
#define HID  128
#define OC4  512   // 4*HID

typedef unsigned long long ull;

// scratch for z_is: [b][h][oc][w]
__device__ float g_z[BB * HH * OC4 * WW];
// double-buffered h state: [par][b][ic][w]  (row0 never read -> no init needed)
__device__ float g_h[2 * BB * HID * WW];
// monotonic progress flags: [b][rank] (never reset; base read per launch)
__device__ int   g_flag[BB * 8];

// ---- packed fp32x2 helpers (SASS FFMA2 path, PTX-only) ----------------------
__device__ __forceinline__ ull pk2(float a, float b) {
    ull r; asm("mov.b64 %0, {%1,%2};" : "=l"(r) : "f"(a), "f"(b)); return r;
}
__device__ __forceinline__ ull dup2(float a) {
    ull r; asm("mov.b64 %0, {%1,%1};" : "=l"(r) : "f"(a)); return r;
}
__device__ __forceinline__ void ffma2(ull& d, ull a, ull b) {
    asm("fma.rn.f32x2 %0, %1, %2, %0;" : "+l"(d) : "l"(a), "l"(b));
}
__device__ __forceinline__ ull add2(ull a, ull b) {
    ull r; asm("add.rn.f32x2 %0, %1, %2;" : "=l"(r) : "l"(a), "l"(b)); return r;
}
__device__ __forceinline__ float lo32(ull a) {
    float x; asm("{ .reg .b32 t; mov.b64 {%0, t}, %1; }" : "=f"(x) : "l"(a)); return x;
}
__device__ __forceinline__ float hi32(ull a) {
    float x; asm("{ .reg .b32 t; mov.b64 {t, %0}, %1; }" : "=f"(x) : "l"(a)); return x;
}

// ---- fast transcendentals (MUFU path; error ~1e-6, budget 1e-3) -------------
__device__ __forceinline__ float fsig(float x) {
    return __fdividef(1.f, 1.f + __expf(-x));
}
__device__ __forceinline__ float ftanh(float x) {
    x = fminf(fmaxf(x, -15.f), 15.f);      // avoid __expf overflow -> NaN
    float t = __expf(-2.f * x);
    return __fdividef(1.f - t, 1.f + t);
}

// ----------------------------------------------------------------------------
// Kernel 1: masked input conv (taps 0,1). Unchanged (known good).
// ----------------------------------------------------------------------------
__global__ void __launch_bounds__(256)
conv_in_kernel(const float* __restrict__ x,
               const float* __restrict__ w_is,
               const float* __restrict__ b_is)
{
    extern __shared__ float smem[];
    float* xs = smem;              // [cin][68], xs[cin][w+1] = x, pads zero
    float* ws = smem + 64 * 68;    // [cin][t(2)][ocl(128)]

    int tid = threadIdx.x;
    int bh  = blockIdx.x;
    int b   = bh >> 6;
    int h   = bh & 63;

    const float* xb = x + ((long)(b * CIN) * HH + h) * WW;
    for (int i = tid; i < CIN * WW; i += 256) {
        int cin = i >> 6, w = i & 63;
        xs[cin * 68 + w + 1] = xb[(long)cin * HH * WW + w];
    }
    if (tid < 64) {
        xs[tid * 68 + 0]  = 0.f;
        xs[tid * 68 + 65] = 0.f;
        xs[tid * 68 + 66] = 0.f;
        xs[tid * 68 + 67] = 0.f;
    }
    __syncthreads();

    int ocl = tid & 63;       // lane-consecutive -> conflict-free W
    int wb  = tid >> 6;       // warp-uniform     -> broadcast x
    int w0  = wb * 16;

    for (int p = 0; p < 4; p++) {
        int ocbase = p * 128;
        for (int i = tid; i < 128 * 192; i += 256) {
            int ol = i / 192, r = i % 192;
            int cin = r / 3, t = r % 3;
            float v = w_is[(long)(ocbase + ol) * 192 + r];
            if (t < 2) ws[(cin * 2 + t) * 128 + ol] = v;
        }
        __syncthreads();

        float acc0[16], acc1[16];
        float bb0 = b_is[ocbase + ocl];
        float bb1 = b_is[ocbase + ocl + 64];
#pragma unroll
        for (int j = 0; j < 16; j++) { acc0[j] = bb0; acc1[j] = bb1; }

        for (int cin = 0; cin < 64; cin++) {
            float w00 = ws[(cin * 2 + 0) * 128 + ocl];
            float w01 = ws[(cin * 2 + 1) * 128 + ocl];
            float w10 = ws[(cin * 2 + 0) * 128 + ocl + 64];
            float w11 = ws[(cin * 2 + 1) * 128 + ocl + 64];
            float xv[20];
            const float4* xp = reinterpret_cast<const float4*>(&xs[cin * 68 + w0]);
            *(float4*)&xv[0]  = xp[0];
            *(float4*)&xv[4]  = xp[1];
            *(float4*)&xv[8]  = xp[2];
            *(float4*)&xv[12] = xp[3];
            *(float4*)&xv[16] = xp[4];
#pragma unroll
            for (int j = 0; j < 16; j++) {
                acc0[j] = fmaf(xv[j],     w00, acc0[j]);
                acc0[j] = fmaf(xv[j + 1], w01, acc0[j]);
                acc1[j] = fmaf(xv[j],     w10, acc1[j]);
                acc1[j] = fmaf(xv[j + 1], w11, acc1[j]);
            }
        }

        float* z0 = &g_z[((long)bh * OC4 + ocbase + ocl)      * WW + w0];
        float* z1 = &g_z[((long)bh * OC4 + ocbase + ocl + 64) * WW + w0];
#pragma unroll
        for (int j = 0; j < 16; j += 4) {
            *(float4*)&z0[j] = make_float4(acc0[j], acc0[j+1], acc0[j+2], acc0[j+3]);
            *(float4*)&z1[j] = make_float4(acc1[j], acc1[j+1], acc1[j+2], acc1[j+3]);
        }
        __syncthreads();
    }
}

// ----------------------------------------------------------------------------
// Kernel 2: row scan, phase-split + 1-wf weight loads + MUFU gates.
// 512 threads. l = tid&63, wb = tid>>6 (8-wide w-blocks, broadcast h).
// ----------------------------------------------------------------------------
#define CONV_IC(ic)                                                          \
    do {                                                                     \
        ull w0d = dup2(Wsm[((ic) * 3 + 0) * 64 + l]);                        \
        ull w1d = dup2(Wsm[((ic) * 3 + 1) * 64 + l]);                        \
        ull w2d = dup2(Wsm[((ic) * 3 + 2) * 64 + l]);                        \
        const float* hrow = &hs[(ic) * 68 + w0];                             \
        ull A[5];                                                            \
        ulonglong2 q0 = *(const ulonglong2*)(hrow);                          \
        ulonglong2 q1 = *(const ulonglong2*)(hrow + 4);                      \
        A[0] = q0.x; A[1] = q0.y; A[2] = q1.x; A[3] = q1.y;                  \
        A[4] = *(const ull*)(hrow + 8);                                      \
        _Pragma("unroll")                                                    \
        for (int k = 0; k < 4; k++) {                                        \
            ffma2(acc[k], A[k],     w0d);                                    \
            ffma2(acc[k], A[k + 1], w2d);                                    \
            ffma2(T[k],   A[k],     w1d);                                    \
        }                                                                    \
        ffma2(T[4], A[4], w1d);                                              \
    } while (0)

__global__ void __launch_bounds__(512)
scan_kernel(const float* __restrict__ w_ss,
            const float* __restrict__ b_ss,
            float* __restrict__ out)
{
    extern __shared__ float smem[];
    float* Wsm  = smem;                    // [(ic*3+t)][64 l]   24576 floats
    float* hs   = Wsm + 128 * 3 * 64;      // [128 ic][68]        8704 floats
    float* zbuf = hs + 128 * 68;           // [64 l][68 pad]      4352 floats
    float* cs   = zbuf + 64 * 68;          // [16 hcl][64 w]      1024 floats

    int tid  = threadIdx.x;
    int rank = blockIdx.x & 7;
    int b    = blockIdx.x >> 3;
    int o0   = rank * 16;                  // own ic range [o0, o0+16)

    volatile int* flags = g_flag + b * 8;
    int base = flags[rank];                // own flag: race-free, launch-uniform

    // stage recurrent weights: Wsm[(ic*3+t)*64 + l] = w_ss[ocg(l)][ic][t]
    for (int i = tid; i < 128 * 3 * 64; i += 512) {
        int ic = i / 192, r = i % 192;
        int t = r >> 6, lx = r & 63;
        int ocgx = (lx >> 4) * 128 + o0 + (lx & 15);
        Wsm[(ic * 3 + t) * 64 + lx] = w_ss[((long)ocgx * 128 + ic) * 3 + t];
    }
    // zero full hs (row 0: h0 = 0) and c state
    for (int i = tid; i < 128 * 68; i += 512) hs[i] = 0.f;
    for (int i = tid; i < 16 * 64; i += 512) cs[i] = 0.f;
    __syncthreads();

    int l  = tid & 63;        // gate g = l>>4, local hid = l&15
    int wb = tid >> 6;        // 0..7, warp-uniform
    int w0 = wb * 8;
    int ocg = (l >> 4) * 128 + o0 + (l & 15);
    ull bias2 = dup2(b_ss[ocg]);

    for (int row = 0; row < HH; row++) {
        int par  = row & 1;
        int par1 = par ^ 1;

        // ---- phase A: issue z loads (DRAM-cold), conv over OWN 16 ic ----
        ull zv[4];
        {
            const ulonglong2* zp = (const ulonglong2*)
                &g_z[(((long)b * HH + row) * OC4 + ocg) * WW + w0];
            ulonglong2 v0 = zp[0], v1 = zp[1];
            zv[0] = v0.x; zv[1] = v0.y; zv[2] = v1.x; zv[3] = v1.y;
        }
        ull acc[4], T[5];
#pragma unroll
        for (int k = 0; k < 4; k++) acc[k] = 0ull;
#pragma unroll
        for (int k = 0; k < 5; k++) T[k] = 0ull;

#pragma unroll 4
        for (int ic = o0; ic < o0 + 16; ic++) CONV_IC(ic);

        // ---- phase B: wait peers, load their 112 channels, conv the rest ----
        if (row > 0) {
            if (tid < 8) {
                while (flags[tid] < base + row) { }
            }
            __syncthreads();
            const float4* gh4 = (const float4*)&g_h[((long)par * BB + b) * HID * WW];
            for (int i = tid; i < 112 * 16; i += 512) {
                int icl = i >> 4;
                int ic  = icl + (icl >= o0 ? 16 : 0);
                float4 v = gh4[ic * 16 + (i & 15)];
                float* d = &hs[ic * 68 + (i & 15) * 4 + 1];
                d[0] = v.x; d[1] = v.y; d[2] = v.z; d[3] = v.w;
            }
            __syncthreads();

#pragma unroll 4
            for (int ic = 0; ic < o0; ic++) CONV_IC(ic);
#pragma unroll 4
            for (int ic = o0 + 16; ic < 128; ic++) CONV_IC(ic);
        }

        // combine: acc += (z + bias) and shifted tap1
#pragma unroll
        for (int k = 0; k < 4; k++) {
            acc[k] = add2(acc[k], add2(zv[k], bias2));
            acc[k] = add2(acc[k], pk2(hi32(T[k]), lo32(T[k + 1])));
        }
#pragma unroll
        for (int k = 0; k < 4; k++)
            *(ull*)&zbuf[l * 68 + w0 + 2 * k] = acc[k];
        __syncthreads();

        // ---- phase C: gates (MUFU); write out, own h -> smem + global ----
        float* ghw = &g_h[((long)par1 * BB + b) * HID * WW];
#pragma unroll
        for (int k = 0; k < 2; k++) {
            int idx = tid + k * 512;
            int hcl = idx >> 6, w = idx & 63;
            float zi  = zbuf[(0  + hcl) * 68 + w];
            float zf  = zbuf[(16 + hcl) * 68 + w];
            float zo  = zbuf[(32 + hcl) * 68 + w];
            float zg2 = zbuf[(48 + hcl) * 68 + w];
            float ig = fsig(zi);
            float fg = fsig(zf);
            float og = fsig(zo);
            float gg = ftanh(zg2);
            float c = fg * cs[hcl * 64 + w] + ig * gg;
            cs[hcl * 64 + w] = c;
            float hv2 = og * ftanh(c);
            int ch = o0 + hcl;
            out[(((long)b * HID + ch) * HH + row) * WW + w] = hv2;
            if (row < HH - 1) {
                ghw[ch * WW + w] = hv2;            // publish to peers
                hs[ch * 68 + w + 1] = hv2;         // own copy for next phase A
            }
        }

        if (row < HH - 1) {
            __threadfence();
            __syncthreads();                       // orders hs writes too
            if (tid == 0) flags[rank] = base + row + 1;
        }
    }
}

// ----------------------------------------------------------------------------
extern "C" void kernel_launch(void* const* d_in, const int* in_sizes, int n_in,
                              void* d_out, int out_size)
{
    (void)in_sizes; (void)n_in; (void)out_size;
    const float* x    = (const float*)d_in[0];
    const float* w_is = (const float*)d_in[1];
    const float* b_is = (const float*)d_in[2];
    const float* w_ss = (const float*)d_in[3];
    const float* b_ss = (const float*)d_in[4];
    float* out = (float*)d_out;

    const int conv_smem = (64 * 68 + 64 * 2 * 128) * 4;                      // 82944 B
    const int scan_smem = (128 * 3 * 64 + 128 * 68 + 64 * 68 + 16 * 64) * 4; // 154624 B

    cudaFuncSetAttribute(conv_in_kernel, cudaFuncAttributeMaxDynamicSharedMemorySize, conv_smem);
    cudaFuncSetAttribute(scan_kernel,    cudaFuncAttributeMaxDynamicSharedMemorySize, scan_smem);

    conv_in_kernel<<<BB * HH, 256, conv_smem>>>(x, w_is, b_is);
    scan_kernel<<<BB * 8, 512, scan_smem>>>(w_ss, b_ss, out);
}

// round 9
// speedup vs baseline: 1.0791x; 1.0791x over previous
#include <cuda_runtime.h>
#include <cstdint>
#include <math.h>

#define BB   16
#define CIN  64
#define HH   64
#define WW   64
#define HID  128
#define OC4  512   // 4*HID

typedef unsigned long long ull;

// scratch for z_is: [b][h][oc][w]
__device__ float g_z[BB * HH * OC4 * WW];
// double-buffered h state: [par][b][ic][w]  (row0 never read -> no init needed)
__device__ float g_h[2 * BB * HID * WW];
// monotonic progress flags: [b][rank] (never reset; base read per launch)
__device__ int   g_flag[BB * 8];

// ---- packed fp32x2 helpers (SASS FFMA2 path, PTX-only) ----------------------
__device__ __forceinline__ ull pk2(float a, float b) {
    ull r; asm("mov.b64 %0, {%1,%2};" : "=l"(r) : "f"(a), "f"(b)); return r;
}
__device__ __forceinline__ ull dup2(float a) {
    ull r; asm("mov.b64 %0, {%1,%1};" : "=l"(r) : "f"(a)); return r;
}
__device__ __forceinline__ void ffma2(ull& d, ull a, ull b) {
    asm("fma.rn.f32x2 %0, %1, %2, %0;" : "+l"(d) : "l"(a), "l"(b));
}
__device__ __forceinline__ ull add2(ull a, ull b) {
    ull r; asm("add.rn.f32x2 %0, %1, %2;" : "=l"(r) : "l"(a), "l"(b)); return r;
}
__device__ __forceinline__ float lo32(ull a) {
    float x; asm("{ .reg .b32 t; mov.b64 {%0, t}, %1; }" : "=f"(x) : "l"(a)); return x;
}
__device__ __forceinline__ float hi32(ull a) {
    float x; asm("{ .reg .b32 t; mov.b64 {t, %0}, %1; }" : "=f"(x) : "l"(a)); return x;
}

// ---- fast transcendentals (MUFU path; error ~1e-6, budget 1e-3) -------------
__device__ __forceinline__ float fsig(float x) {
    return __fdividef(1.f, 1.f + __expf(-x));
}
__device__ __forceinline__ float ftanh(float x) {
    x = fminf(fmaxf(x, -15.f), 15.f);      // avoid __expf overflow -> NaN
    float t = __expf(-2.f * x);
    return __fdividef(1.f - t, 1.f + t);
}

// ---- scoped release/acquire flag ops (replaces __threadfence) ---------------
__device__ __forceinline__ void st_release(int* p, int v) {
    asm volatile("st.release.gpu.global.s32 [%0], %1;" :: "l"(p), "r"(v) : "memory");
}
__device__ __forceinline__ int ld_acquire(int* p) {
    int v;
    asm volatile("ld.acquire.gpu.global.s32 %0, [%1];" : "=r"(v) : "l"(p) : "memory");
    return v;
}

// ----------------------------------------------------------------------------
// Kernel 1: masked input conv (taps 0,1). Unchanged (known good).
// ----------------------------------------------------------------------------
__global__ void __launch_bounds__(256)
conv_in_kernel(const float* __restrict__ x,
               const float* __restrict__ w_is,
               const float* __restrict__ b_is)
{
    extern __shared__ float smem[];
    float* xs = smem;              // [cin][68], xs[cin][w+1] = x, pads zero
    float* ws = smem + 64 * 68;    // [cin][t(2)][ocl(128)]

    int tid = threadIdx.x;
    int bh  = blockIdx.x;
    int b   = bh >> 6;
    int h   = bh & 63;

    const float* xb = x + ((long)(b * CIN) * HH + h) * WW;
    for (int i = tid; i < CIN * WW; i += 256) {
        int cin = i >> 6, w = i & 63;
        xs[cin * 68 + w + 1] = xb[(long)cin * HH * WW + w];
    }
    if (tid < 64) {
        xs[tid * 68 + 0]  = 0.f;
        xs[tid * 68 + 65] = 0.f;
        xs[tid * 68 + 66] = 0.f;
        xs[tid * 68 + 67] = 0.f;
    }
    __syncthreads();

    int ocl = tid & 63;       // lane-consecutive -> conflict-free W
    int wb  = tid >> 6;       // warp-uniform     -> broadcast x
    int w0  = wb * 16;

    for (int p = 0; p < 4; p++) {
        int ocbase = p * 128;
        for (int i = tid; i < 128 * 192; i += 256) {
            int ol = i / 192, r = i % 192;
            int cin = r / 3, t = r % 3;
            float v = w_is[(long)(ocbase + ol) * 192 + r];
            if (t < 2) ws[(cin * 2 + t) * 128 + ol] = v;
        }
        __syncthreads();

        float acc0[16], acc1[16];
        float bb0 = b_is[ocbase + ocl];
        float bb1 = b_is[ocbase + ocl + 64];
#pragma unroll
        for (int j = 0; j < 16; j++) { acc0[j] = bb0; acc1[j] = bb1; }

        for (int cin = 0; cin < 64; cin++) {
            float w00 = ws[(cin * 2 + 0) * 128 + ocl];
            float w01 = ws[(cin * 2 + 1) * 128 + ocl];
            float w10 = ws[(cin * 2 + 0) * 128 + ocl + 64];
            float w11 = ws[(cin * 2 + 1) * 128 + ocl + 64];
            float xv[20];
            const float4* xp = reinterpret_cast<const float4*>(&xs[cin * 68 + w0]);
            *(float4*)&xv[0]  = xp[0];
            *(float4*)&xv[4]  = xp[1];
            *(float4*)&xv[8]  = xp[2];
            *(float4*)&xv[12] = xp[3];
            *(float4*)&xv[16] = xp[4];
#pragma unroll
            for (int j = 0; j < 16; j++) {
                acc0[j] = fmaf(xv[j],     w00, acc0[j]);
                acc0[j] = fmaf(xv[j + 1], w01, acc0[j]);
                acc1[j] = fmaf(xv[j],     w10, acc1[j]);
                acc1[j] = fmaf(xv[j + 1], w11, acc1[j]);
            }
        }

        float* z0 = &g_z[((long)bh * OC4 + ocbase + ocl)      * WW + w0];
        float* z1 = &g_z[((long)bh * OC4 + ocbase + ocl + 64) * WW + w0];
#pragma unroll
        for (int j = 0; j < 16; j += 4) {
            *(float4*)&z0[j] = make_float4(acc0[j], acc0[j+1], acc0[j+2], acc0[j+3]);
            *(float4*)&z1[j] = make_float4(acc1[j], acc1[j+1], acc1[j+2], acc1[j+3]);
        }
        __syncthreads();
    }
}

// ----------------------------------------------------------------------------
// Kernel 2: row scan, phase-split, 256 threads x 16 w/thread (instruction-
// economy config). l = tid&63, wb = tid>>6 in 0..3. float4 weight loads,
// MUFU gates, release/acquire cross-CTA sync.
// ----------------------------------------------------------------------------
#define CONV_IC(ic)                                                          \
    do {                                                                     \
        const float4 wv = *(const float4*)&Wq[(ic) * 256 + l * 4];           \
        ull w0d = dup2(wv.x), w1d = dup2(wv.y), w2d = dup2(wv.z);            \
        const float* hrow = &hs[(ic) * 68 + w0];                             \
        ull A[9];                                                            \
        ulonglong2 q0 = *(const ulonglong2*)(hrow);                          \
        ulonglong2 q1 = *(const ulonglong2*)(hrow + 4);                      \
        ulonglong2 q2 = *(const ulonglong2*)(hrow + 8);                      \
        ulonglong2 q3 = *(const ulonglong2*)(hrow + 12);                     \
        A[0] = q0.x; A[1] = q0.y; A[2] = q1.x; A[3] = q1.y;                  \
        A[4] = q2.x; A[5] = q2.y; A[6] = q3.x; A[7] = q3.y;                  \
        A[8] = *(const ull*)(hrow + 16);                                     \
        _Pragma("unroll")                                                    \
        for (int k = 0; k < 8; k++) {                                        \
            ffma2(acc[k], A[k],     w0d);                                    \
            ffma2(acc[k], A[k + 1], w2d);                                    \
            ffma2(T[k],   A[k],     w1d);                                    \
        }                                                                    \
        ffma2(T[8], A[8], w1d);                                              \
    } while (0)

__global__ void __launch_bounds__(256)
scan_kernel(const float* __restrict__ w_ss,
            const float* __restrict__ b_ss,
            float* __restrict__ out)
{
    extern __shared__ float smem[];
    float* Wq   = smem;                    // [ic][64 l][4]      32768 floats
    float* hs   = Wq + 128 * 64 * 4;       // [128 ic][68]        8704 floats
    float* zbuf = hs + 128 * 68;           // [64 l][68 pad]      4352 floats
    float* cs   = zbuf + 64 * 68;          // [16 hcl][64 w]      1024 floats

    int tid  = threadIdx.x;
    int rank = blockIdx.x & 7;
    int b    = blockIdx.x >> 3;
    int o0   = rank * 16;                  // own ic range [o0, o0+16)

    int* flags = g_flag + b * 8;
    int base = *(volatile int*)(flags + rank);   // own flag: race-free

    // stage packed weights: Wq[ic][l][0..2] = w_ss[ocg(l)][ic][t], [3]=0
    for (int i = tid; i < 128 * 64 * 4; i += 256) {
        int t = i & 3, lx = (i >> 2) & 63, ic = i >> 8;
        int ocgx = (lx >> 4) * 128 + o0 + (lx & 15);
        Wq[i] = (t < 3) ? w_ss[((long)ocgx * 128 + ic) * 3 + t] : 0.f;
    }
    // zero full hs (row 0: h0 = 0) and c state
    for (int i = tid; i < 128 * 68; i += 256) hs[i] = 0.f;
    for (int i = tid; i < 16 * 64; i += 256) cs[i] = 0.f;
    __syncthreads();

    int l  = tid & 63;        // gate g = l>>4, local hid = l&15
    int wb = tid >> 6;        // 0..3, warp-uniform
    int w0 = wb * 16;
    int ocg = (l >> 4) * 128 + o0 + (l & 15);
    ull bias2 = dup2(b_ss[ocg]);

    for (int row = 0; row < HH; row++) {
        int par  = row & 1;
        int par1 = par ^ 1;

        // ---- phase A: issue z loads (DRAM-cold), conv over OWN 16 ic ----
        ull zv[8];
        {
            const ulonglong2* zp = (const ulonglong2*)
                &g_z[(((long)b * HH + row) * OC4 + ocg) * WW + w0];
#pragma unroll
            for (int q = 0; q < 4; q++) {
                ulonglong2 v = zp[q];
                zv[2 * q] = v.x; zv[2 * q + 1] = v.y;
            }
        }
        ull acc[8], T[9];
#pragma unroll
        for (int k = 0; k < 8; k++) acc[k] = 0ull;
#pragma unroll
        for (int k = 0; k < 9; k++) T[k] = 0ull;

#pragma unroll 4
        for (int ic = o0; ic < o0 + 16; ic++) CONV_IC(ic);

        // ---- phase B: wait peers, load their 112 channels, conv the rest ----
        if (row > 0) {
            if (tid < 8) {
                while (ld_acquire(flags + tid) < base + row) { }
            }
            __syncthreads();
            const float4* gh4 = (const float4*)&g_h[((long)par * BB + b) * HID * WW];
            for (int i = tid; i < 112 * 16; i += 256) {
                int icl = i >> 4;
                int ic  = icl + (icl >= o0 ? 16 : 0);
                float4 v = gh4[ic * 16 + (i & 15)];
                float* d = &hs[ic * 68 + (i & 15) * 4 + 1];
                d[0] = v.x; d[1] = v.y; d[2] = v.z; d[3] = v.w;
            }
            __syncthreads();

#pragma unroll 4
            for (int ic = 0; ic < o0; ic++) CONV_IC(ic);
#pragma unroll 4
            for (int ic = o0 + 16; ic < 128; ic++) CONV_IC(ic);
        }

        // combine: acc += (z + bias) and shifted tap1
#pragma unroll
        for (int k = 0; k < 8; k++) {
            acc[k] = add2(acc[k], add2(zv[k], bias2));
            acc[k] = add2(acc[k], pk2(hi32(T[k]), lo32(T[k + 1])));
        }
#pragma unroll
        for (int k = 0; k < 8; k++)
            *(ull*)&zbuf[l * 68 + w0 + 2 * k] = acc[k];
        __syncthreads();

        // ---- phase C: gates (MUFU); write out, own h -> smem + global ----
        float* ghw = &g_h[((long)par1 * BB + b) * HID * WW];
#pragma unroll
        for (int k = 0; k < 4; k++) {
            int idx = tid + k * 256;
            int hcl = idx >> 6, w = idx & 63;
            float zi  = zbuf[(0  + hcl) * 68 + w];
            float zf  = zbuf[(16 + hcl) * 68 + w];
            float zo  = zbuf[(32 + hcl) * 68 + w];
            float zg2 = zbuf[(48 + hcl) * 68 + w];
            float ig = fsig(zi);
            float fg = fsig(zf);
            float og = fsig(zo);
            float gg = ftanh(zg2);
            float c = fg * cs[hcl * 64 + w] + ig * gg;
            cs[hcl * 64 + w] = c;
            float hv2 = og * ftanh(c);
            int ch = o0 + hcl;
            out[(((long)b * HID + ch) * HH + row) * WW + w] = hv2;
            if (row < HH - 1) {
                ghw[ch * WW + w] = hv2;            // publish to peers
                hs[ch * 68 + w + 1] = hv2;         // own copy for next phase A
            }
        }

        if (row < HH - 1) {
            __syncthreads();                       // all writes happen-before tid0
            if (tid == 0) st_release(flags + rank, base + row + 1);
        }
    }
}

// ----------------------------------------------------------------------------
extern "C" void kernel_launch(void* const* d_in, const int* in_sizes, int n_in,
                              void* d_out, int out_size)
{
    (void)in_sizes; (void)n_in; (void)out_size;
    const float* x    = (const float*)d_in[0];
    const float* w_is = (const float*)d_in[1];
    const float* b_is = (const float*)d_in[2];
    const float* w_ss = (const float*)d_in[3];
    const float* b_ss = (const float*)d_in[4];
    float* out = (float*)d_out;

    const int conv_smem = (64 * 68 + 64 * 2 * 128) * 4;                        // 82944 B
    const int scan_smem = (128 * 64 * 4 + 128 * 68 + 64 * 68 + 16 * 64) * 4;   // 187392 B

    cudaFuncSetAttribute(conv_in_kernel, cudaFuncAttributeMaxDynamicSharedMemorySize, conv_smem);
    cudaFuncSetAttribute(scan_kernel,    cudaFuncAttributeMaxDynamicSharedMemorySize, scan_smem);

    conv_in_kernel<<<BB * HH, 256, conv_smem>>>(x, w_is, b_is);
    scan_kernel<<<BB * 8, 256, scan_smem>>>(w_ss, b_ss, out);
}

// round 10
// speedup vs baseline: 1.1966x; 1.1088x over previous
#include <cuda_runtime.h>
#include <cstdint>
#include <math.h>

#define BB   16
#define CIN  64
#define HH   64
#define WW   64
#define HID  128
#define OC4  512   // 4*HID

typedef unsigned long long ull;

// double-buffered h state: [par][b][ic][w]  (row0 never read -> no init needed)
__device__ float g_h[2 * BB * HID * WW];
// monotonic progress flags: [b][rank] (never reset; base read per launch)
__device__ int   g_flag[BB * 8];

// ---- packed fp32x2 helpers (SASS FFMA2 path, PTX-only) ----------------------
__device__ __forceinline__ ull pk2(float a, float b) {
    ull r; asm("mov.b64 %0, {%1,%2};" : "=l"(r) : "f"(a), "f"(b)); return r;
}
__device__ __forceinline__ ull dup2(float a) {
    ull r; asm("mov.b64 %0, {%1,%1};" : "=l"(r) : "f"(a)); return r;
}
__device__ __forceinline__ void ffma2(ull& d, ull a, ull b) {
    asm("fma.rn.f32x2 %0, %1, %2, %0;" : "+l"(d) : "l"(a), "l"(b));
}
__device__ __forceinline__ ull add2(ull a, ull b) {
    ull r; asm("add.rn.f32x2 %0, %1, %2;" : "=l"(r) : "l"(a), "l"(b)); return r;
}
__device__ __forceinline__ float lo32(ull a) {
    float x; asm("{ .reg .b32 t; mov.b64 {%0, t}, %1; }" : "=f"(x) : "l"(a)); return x;
}
__device__ __forceinline__ float hi32(ull a) {
    float x; asm("{ .reg .b32 t; mov.b64 {t, %0}, %1; }" : "=f"(x) : "l"(a)); return x;
}

// ---- fast transcendentals (MUFU path; error ~1e-6, budget 1e-3) -------------
__device__ __forceinline__ float fsig(float x) {
    return __fdividef(1.f, 1.f + __expf(-x));
}
__device__ __forceinline__ float ftanh(float x) {
    x = fminf(fmaxf(x, -15.f), 15.f);      // avoid __expf overflow -> NaN
    float t = __expf(-2.f * x);
    return __fdividef(1.f - t, 1.f + t);
}

// ---- scoped release/acquire flag ops ----------------------------------------
__device__ __forceinline__ void st_release(int* p, int v) {
    asm volatile("st.release.gpu.global.s32 [%0], %1;" :: "l"(p), "r"(v) : "memory");
}
__device__ __forceinline__ int ld_acquire(int* p) {
    int v;
    asm volatile("ld.acquire.gpu.global.s32 %0, [%1];" : "=r"(v) : "l"(p) : "memory");
    return v;
}

// ----------------------------------------------------------------------------
// Fused kernel: input conv + row scan in one persistent pass.
// 8 CTAs per batch, 256 threads. l = tid&63 (64 oc slots), wb = tid>>6 (16 w).
// Wq float4: .xyz = w_ss taps, .w slot ic encodes w_is[cin=ic>>1][tap=ic&1].
// Phase A (pre-wait): x-conv (64 cin) + own-16-ic h-conv.
// Phase B: flag wait, peer-h copy + xs prefetch for next row, h-conv 112 ic.
// ----------------------------------------------------------------------------
#define CONV_IC(ic)                                                          \
    do {                                                                     \
        const float4 wv = *(const float4*)&Wq[(ic) * 256 + l * 4];           \
        ull w0d = dup2(wv.x), w1d = dup2(wv.y), w2d = dup2(wv.z);            \
        const float* hrow = &hs[(ic) * 68 + w0];                             \
        ull A[9];                                                            \
        ulonglong2 q0 = *(const ulonglong2*)(hrow);                          \
        ulonglong2 q1 = *(const ulonglong2*)(hrow + 4);                      \
        ulonglong2 q2 = *(const ulonglong2*)(hrow + 8);                      \
        ulonglong2 q3 = *(const ulonglong2*)(hrow + 12);                     \
        A[0] = q0.x; A[1] = q0.y; A[2] = q1.x; A[3] = q1.y;                  \
        A[4] = q2.x; A[5] = q2.y; A[6] = q3.x; A[7] = q3.y;                  \
        A[8] = *(const ull*)(hrow + 16);                                     \
        _Pragma("unroll")                                                    \
        for (int k = 0; k < 8; k++) {                                        \
            ffma2(acc[k], A[k],     w0d);                                    \
            ffma2(acc[k], A[k + 1], w2d);                                    \
            ffma2(T[k],   A[k],     w1d);                                    \
        }                                                                    \
        ffma2(T[8], A[8], w1d);                                              \
    } while (0)

#define CONV_X(cin)                                                          \
    do {                                                                     \
        ull wAd = dup2(Wq[(2 * (cin))     * 256 + l * 4 + 3]);               \
        ull wBd = dup2(Wq[(2 * (cin) + 1) * 256 + l * 4 + 3]);               \
        const float* xrow = &xs[(cin) * 68 + w0];                            \
        ull A[9];                                                            \
        ulonglong2 q0 = *(const ulonglong2*)(xrow);                          \
        ulonglong2 q1 = *(const ulonglong2*)(xrow + 4);                      \
        ulonglong2 q2 = *(const ulonglong2*)(xrow + 8);                      \
        ulonglong2 q3 = *(const ulonglong2*)(xrow + 12);                     \
        A[0] = q0.x; A[1] = q0.y; A[2] = q1.x; A[3] = q1.y;                  \
        A[4] = q2.x; A[5] = q2.y; A[6] = q3.x; A[7] = q3.y;                  \
        A[8] = *(const ull*)(xrow + 16);                                     \
        _Pragma("unroll")                                                    \
        for (int k = 0; k < 8; k++) {                                        \
            ffma2(acc[k], A[k], wAd);                                        \
            ffma2(T[k],   A[k], wBd);                                        \
        }                                                                    \
        ffma2(T[8], A[8], wBd);                                              \
    } while (0)

__global__ void __launch_bounds__(256)
scan_kernel(const float* __restrict__ x,
            const float* __restrict__ w_is,
            const float* __restrict__ b_is,
            const float* __restrict__ w_ss,
            const float* __restrict__ b_ss,
            float* __restrict__ out)
{
    extern __shared__ float smem[];
    float* Wq   = smem;                    // [ic][64 l][4]      32768 floats
    float* hs   = Wq + 128 * 64 * 4;       // [128 ic][68]        8704 floats
    float* xs   = hs + 128 * 68;           // [64 cin][68]        4352 floats
    float* zbuf = xs + 64 * 68;            // [64 l][64]          4096 floats
    float* cs   = zbuf + 64 * 64;          // [16 hcl][64 w]      1024 floats

    int tid  = threadIdx.x;
    int rank = blockIdx.x & 7;
    int b    = blockIdx.x >> 3;
    int o0   = rank * 16;                  // own ic range [o0, o0+16)

    int* flags = g_flag + b * 8;
    int base = *(volatile int*)(flags + rank);   // own flag: race-free

    // stage packed weights: Wq[ic][l] = (w_ss t0,t1,t2, w_is[ic>>1][ic&1])
    for (int i = tid; i < 128 * 64 * 4; i += 256) {
        int t = i & 3, lx = (i >> 2) & 63, ic = i >> 8;
        int ocgx = (lx >> 4) * 128 + o0 + (lx & 15);
        float v;
        if (t < 3) v = w_ss[((long)ocgx * 128 + ic) * 3 + t];
        else       v = w_is[(long)ocgx * 192 + (ic >> 1) * 3 + (ic & 1)];
        Wq[i] = v;
    }
    // zero hs (row 0: h0 = 0), xs (pads persist), c state
    for (int i = tid; i < 128 * 68; i += 256) hs[i] = 0.f;
    for (int i = tid; i < 64 * 68; i += 256)  xs[i] = 0.f;
    for (int i = tid; i < 16 * 64; i += 256)  cs[i] = 0.f;
    __syncthreads();
    // load x row 0: x[b][cin][0][w]
    {
        const float* xb = x + (long)b * CIN * HH * WW;
        for (int i = tid; i < 1024; i += 256) {       // float4 index
            int cin = i >> 4, wq = (i & 15) * 4;
            float4 v = *(const float4*)&xb[((long)cin * HH + 0) * WW + wq];
            float* d = &xs[cin * 68 + wq + 1];
            d[0] = v.x; d[1] = v.y; d[2] = v.z; d[3] = v.w;
        }
    }
    __syncthreads();

    int l  = tid & 63;        // gate g = l>>4, local hid = l&15
    int wb = tid >> 6;        // 0..3, warp-uniform
    int w0 = wb * 16;
    int ocg = (l >> 4) * 128 + o0 + (l & 15);
    ull bias2 = dup2(b_ss[ocg] + b_is[ocg]);   // both biases folded

    for (int row = 0; row < HH; row++) {
        int par  = row & 1;
        int par1 = par ^ 1;

        // ---- phase A: fused input conv (64 cin) + own-16-ic h-conv ----
        ull acc[8], T[9];
#pragma unroll
        for (int k = 0; k < 8; k++) acc[k] = 0ull;
#pragma unroll
        for (int k = 0; k < 9; k++) T[k] = 0ull;

#pragma unroll 4
        for (int cin = 0; cin < 64; cin++) CONV_X(cin);
#pragma unroll 4
        for (int ic = o0; ic < o0 + 16; ic++) CONV_IC(ic);

        // ---- phase B: wait peers; refill xs(row+1); copy peer h; conv rest --
        if (row > 0) {
            if (tid < 8) {
                while (ld_acquire(flags + tid) < base + row) { }
            }
        }
        __syncthreads();                 // xs/hs reads of phase A complete

        if (row < HH - 1) {              // prefetch next x row (no dependency)
            const float* xb = x + (long)b * CIN * HH * WW;
            for (int i = tid; i < 1024; i += 256) {
                int cin = i >> 4, wq = (i & 15) * 4;
                float4 v = *(const float4*)&xb[((long)cin * HH + row + 1) * WW + wq];
                float* d = &xs[cin * 68 + wq + 1];
                d[0] = v.x; d[1] = v.y; d[2] = v.z; d[3] = v.w;
            }
        }
        if (row > 0) {
            const float4* gh4 = (const float4*)&g_h[((long)par * BB + b) * HID * WW];
            for (int i = tid; i < 112 * 16; i += 256) {
                int icl = i >> 4;
                int ic  = icl + (icl >= o0 ? 16 : 0);
                float4 v = gh4[ic * 16 + (i & 15)];
                float* d = &hs[ic * 68 + (i & 15) * 4 + 1];
                d[0] = v.x; d[1] = v.y; d[2] = v.z; d[3] = v.w;
            }
            __syncthreads();

#pragma unroll 4
            for (int ic = 0; ic < o0; ic++) CONV_IC(ic);
#pragma unroll 4
            for (int ic = o0 + 16; ic < 128; ic++) CONV_IC(ic);
        }

        // combine: acc += bias and shifted tap1/odd-tap accumulator
#pragma unroll
        for (int k = 0; k < 8; k++) {
            acc[k] = add2(acc[k], bias2);
            acc[k] = add2(acc[k], pk2(hi32(T[k]), lo32(T[k + 1])));
        }
#pragma unroll
        for (int k = 0; k < 8; k++)
            *(ull*)&zbuf[l * 64 + w0 + 2 * k] = acc[k];
        __syncthreads();

        // ---- phase C: gates (MUFU); write out, own h -> smem + global ----
        float* ghw = &g_h[((long)par1 * BB + b) * HID * WW];
#pragma unroll
        for (int k = 0; k < 4; k++) {
            int idx = tid + k * 256;
            int hcl = idx >> 6, w = idx & 63;
            float zi  = zbuf[(0  + hcl) * 64 + w];
            float zf  = zbuf[(16 + hcl) * 64 + w];
            float zo  = zbuf[(32 + hcl) * 64 + w];
            float zg2 = zbuf[(48 + hcl) * 64 + w];
            float ig = fsig(zi);
            float fg = fsig(zf);
            float og = fsig(zo);
            float gg = ftanh(zg2);
            float c = fg * cs[hcl * 64 + w] + ig * gg;
            cs[hcl * 64 + w] = c;
            float hv2 = og * ftanh(c);
            int ch = o0 + hcl;
            out[(((long)b * HID + ch) * HH + row) * WW + w] = hv2;
            if (row < HH - 1) {
                ghw[ch * WW + w] = hv2;            // publish to peers
                hs[ch * 68 + w + 1] = hv2;         // own copy for next phase A
            }
        }

        if (row < HH - 1) {
            __syncthreads();                       // all writes happen-before tid0
            if (tid == 0) st_release(flags + rank, base + row + 1);
        }
    }
}

// ----------------------------------------------------------------------------
extern "C" void kernel_launch(void* const* d_in, const int* in_sizes, int n_in,
                              void* d_out, int out_size)
{
    (void)in_sizes; (void)n_in; (void)out_size;
    const float* x    = (const float*)d_in[0];
    const float* w_is = (const float*)d_in[1];
    const float* b_is = (const float*)d_in[2];
    const float* w_ss = (const float*)d_in[3];
    const float* b_ss = (const float*)d_in[4];
    float* out = (float*)d_out;

    const int scan_smem = (128 * 64 * 4 + 128 * 68 + 64 * 68 + 64 * 64 + 16 * 64) * 4; // 203776 B

    cudaFuncSetAttribute(scan_kernel, cudaFuncAttributeMaxDynamicSharedMemorySize, scan_smem);

    scan_kernel<<<BB * 8, 256, scan_smem>>>(x, w_is, b_is, w_ss, b_ss, out);
}